// round 15
// baseline (speedup 1.0000x reference)
#include <cuda_runtime.h>
#include <math.h>

// Problem constants (fixed by the dataset)
#define A_   16
#define SK_  2048
#define SQ_  2048
#define D_   128
#define IDM_ 128
#define RR_  3
// T_ANNEAL = 10, t_ANNEAL = 0

// ---------------------------------------------------------------------------
// Scratch (device globals — no allocation allowed)
// ---------------------------------------------------------------------------
__device__ float  g_M[2][A_ * IDM_ * RR_];   // folded projections
__device__ float  g_c[2][A_ * RR_];          // folded bias projections
__device__ float4 g_code[2][A_ * SK_];       // [0] = Kc/3, [1] = Qc

// ---------------------------------------------------------------------------
// Kernel 1 (R13 version, at launch/ramp floor): fold Wk/Wq + bias via W[a].
// ---------------------------------------------------------------------------
__global__ void __launch_bounds__(512, 1) prep_kernel(
        const float* __restrict__ Wk, const float* __restrict__ bk,
        const float* __restrict__ Wq, const float* __restrict__ bq,
        const float* __restrict__ W) {
    const int side = blockIdx.x >> 4;        // 0 = K, 1 = Q
    const int a    = blockIdx.x & 15;
    const float* Wx = side ? Wq : Wk;
    const float* bx = side ? bq : bk;

    const int t  = threadIdx.x;
    const int d  = t & 127;
    const int ep = t >> 7;                   // e-partition 0..3

    float w[32];
#pragma unroll
    for (int i = 0; i < 32; i++)
        w[i] = Wx[(ep * 32 + i) * D_ + d];

    __shared__ float Wsh[IDM_ * RR_];        // W[a] : [128,3]
    __shared__ float red[4][IDM_ * RR_];     // partial sums

    for (int i = t; i < IDM_ * RR_; i += 512) Wsh[i] = W[a * IDM_ * RR_ + i];
    __syncthreads();

    float a0 = 0.f, a1 = 0.f, a2 = 0.f;
#pragma unroll
    for (int i = 0; i < 32; i++) {
        int e = ep * 32 + i;
        a0 = fmaf(w[i], Wsh[e * 3 + 0], a0);
        a1 = fmaf(w[i], Wsh[e * 3 + 1], a1);
        a2 = fmaf(w[i], Wsh[e * 3 + 2], a2);
    }
    red[ep][d * 3 + 0] = a0;
    red[ep][d * 3 + 1] = a1;
    red[ep][d * 3 + 2] = a2;
    __syncthreads();

    if (ep == 0) {
        int base = a * (IDM_ * RR_) + d * RR_;
#pragma unroll
        for (int r = 0; r < RR_; r++) {
            int i = d * 3 + r;
            g_M[side][base + r] = red[0][i] + red[1][i] + red[2][i] + red[3][i];
        }
    }

    if (t < 32) {   // bias fold on warp 0
        float c0 = 0.f, c1 = 0.f, c2 = 0.f;
#pragma unroll
        for (int e = t; e < IDM_; e += 32) {
            float b = bx[e];
            c0 = fmaf(b, Wsh[e * 3 + 0], c0);
            c1 = fmaf(b, Wsh[e * 3 + 1], c1);
            c2 = fmaf(b, Wsh[e * 3 + 2], c2);
        }
#pragma unroll
        for (int o = 16; o > 0; o >>= 1) {
            c0 += __shfl_xor_sync(0xffffffffu, c0, o);
            c1 += __shfl_xor_sync(0xffffffffu, c1, o);
            c2 += __shfl_xor_sync(0xffffffffu, c2, o);
        }
        if (t == 0) {
            g_c[side][a * RR_ + 0] = c0;
            g_c[side][a * RR_ + 1] = c1;
            g_c[side][a * RR_ + 2] = c2;
        }
    }
}

// ---------------------------------------------------------------------------
// Kernel 2: hash codes, 16 rows per warp (MLP=16 on the X loads).
// 48 interleaved shuffle chains; lanes 0..15 write one row each.
// Grid: 512 blocks x 256 threads = 4096 warps x 16 rows = 65536 rows.
// __launch_bounds__(256, 1): ~120 live regs must NOT spill (R12 lesson).
// ---------------------------------------------------------------------------
__global__ void __launch_bounds__(256, 1) code_kernel(
        const float* __restrict__ K, const float* __restrict__ Q) {
    int warp = (blockIdx.x * blockDim.x + threadIdx.x) >> 5;
    int lane = threadIdx.x & 31;
    int grow0 = warp * 16;                   // 16 consecutive rows, same (side,a)
    int which = (grow0 >= A_ * SK_) ? 1 : 0;
    int row0  = which ? (grow0 - A_ * SK_) : grow0;
    int a     = row0 >> 11;

    const float* X = which ? Q : K;
    const float4* Xv = reinterpret_cast<const float4*>(X);
    float4 x[16];
#pragma unroll
    for (int i = 0; i < 16; i++)
        x[i] = Xv[(row0 + i) * (D_ / 4) + lane];

    const float* M = &g_M[which][a * (IDM_ * RR_) + lane * 12];
    float4 m0 = *reinterpret_cast<const float4*>(M);
    float4 m1 = *reinterpret_cast<const float4*>(M + 4);
    float4 m2 = *reinterpret_cast<const float4*>(M + 8);

    float p0[16], p1[16], p2[16];
#pragma unroll
    for (int i = 0; i < 16; i++) {
        p0[i] = x[i].x * m0.x + x[i].y * m0.w + x[i].z * m1.z + x[i].w * m2.y;
        p1[i] = x[i].x * m0.y + x[i].y * m1.x + x[i].z * m1.w + x[i].w * m2.z;
        p2[i] = x[i].x * m0.z + x[i].y * m1.y + x[i].z * m2.x + x[i].w * m2.w;
    }

#pragma unroll
    for (int o = 16; o > 0; o >>= 1) {       // 48 interleaved chains
#pragma unroll
        for (int i = 0; i < 16; i++) {
            p0[i] += __shfl_xor_sync(0xffffffffu, p0[i], o);
            p1[i] += __shfl_xor_sync(0xffffffffu, p1[i], o);
            p2[i] += __shfl_xor_sync(0xffffffffu, p2[i], o);
        }
    }

    // Full sums live in every lane; lanes 0..15 each finish one row.
    if (lane < 16) {
        float s0, s1, s2;
#pragma unroll
        for (int i = 0; i < 16; i++)
            if (lane == i) { s0 = p0[i]; s1 = p1[i]; s2 = p2[i]; }
        const float* c = &g_c[which][a * RR_];
        float scale = which ? 1.0f : (1.0f / 3.0f);   // fold /R into Kc
        float v0 = tanhf((s0 + c[0]) * 0.1f) * scale;
        float v1 = tanhf((s1 + c[1]) * 0.1f) * scale;
        float v2 = tanhf((s2 + c[2]) * 0.1f) * scale;
        g_code[which][row0 + lane] = make_float4(v0, v1, v2, 0.f);
    }
}

// ---------------------------------------------------------------------------
// Kernel 3 (R14 version, near write-roofline): 16 t-rows x 1024 s-cols,
// streaming stores (output never re-read, 2x L2 capacity).
// ---------------------------------------------------------------------------
__device__ __forceinline__ float pc_fn(const float4 q, const float4 k) {
    float x  = fmaf(q.x, k.x, fmaf(q.y, k.y, q.z * k.z));      // Kc already /3
    float t  = x * x;
    float sg = fmaf(x, fmaf(t, -2.0833333e-5f, 0.025f), 0.5f); // sigmoid(x/10)
    return x * sg;
}

__global__ void __launch_bounds__(256) pc_kernel(float* __restrict__ out) {
    const int a     = blockIdx.z;
    const int tbase = blockIdx.y * 16;
    const int sbase = blockIdx.x * 1024;
    const int tid   = threadIdx.x;

    __shared__ float4 qc_sh[16];
    if (tid < 16)
        qc_sh[tid] = g_code[1][a * SQ_ + tbase + tid];

    const float4* kc = &g_code[0][a * SK_ + sbase + tid * 4];
    const float4 k0 = kc[0];
    const float4 k1 = kc[1];
    const float4 k2 = kc[2];
    const float4 k3 = kc[3];
    __syncthreads();

    float* obase = out + ((size_t)(a * SQ_ + tbase)) * SK_ + (size_t)(sbase + tid * 4);
#pragma unroll 4
    for (int j = 0; j < 16; j++) {
        const float4 q = qc_sh[j];        // broadcast LDS
        float4 o;
        o.x = pc_fn(q, k0);
        o.y = pc_fn(q, k1);
        o.z = pc_fn(q, k2);
        o.w = pc_fn(q, k3);
        __stcs(reinterpret_cast<float4*>(obase + (size_t)j * SK_), o);
    }
}

// ---------------------------------------------------------------------------
// Launch
// ---------------------------------------------------------------------------
extern "C" void kernel_launch(void* const* d_in, const int* in_sizes, int n_in,
                              void* d_out, int out_size) {
    const float* K  = (const float*)d_in[0];
    const float* Q  = (const float*)d_in[1];
    const float* Wk = (const float*)d_in[2];
    const float* bk = (const float*)d_in[3];
    const float* Wq = (const float*)d_in[4];
    const float* bq = (const float*)d_in[5];
    const float* W  = (const float*)d_in[6];
    float* out = (float*)d_out;

    prep_kernel<<<2 * A_, 512>>>(Wk, bk, Wq, bq, W);
    code_kernel<<<(2 * A_ * SK_) / 128, 256>>>(K, Q);
    pc_kernel<<<dim3(SK_ / 1024, SQ_ / 16, A_), 256>>>(out);
}

// round 16
// speedup vs baseline: 1.0296x; 1.0296x over previous
#include <cuda_runtime.h>
#include <math.h>

// Problem constants (fixed by the dataset)
#define A_   16
#define SK_  2048
#define SQ_  2048
#define D_   128
#define IDM_ 128
#define RR_  3
// T_ANNEAL = 10, t_ANNEAL = 0

// ---------------------------------------------------------------------------
// Scratch (device globals — no allocation allowed)
// ---------------------------------------------------------------------------
__device__ float  g_M[2][A_ * IDM_ * RR_];   // folded projections
__device__ float  g_c[2][A_ * RR_];          // folded bias projections
__device__ float4 g_code[2][A_ * SK_];       // [0] = Kc/3, [1] = Qc

// ---------------------------------------------------------------------------
// Kernel 1: fold Wk/Wq + bias via W[a].  (R13 version + PDL trigger)
// ---------------------------------------------------------------------------
__global__ void __launch_bounds__(512, 1) prep_kernel(
        const float* __restrict__ Wk, const float* __restrict__ bk,
        const float* __restrict__ Wq, const float* __restrict__ bq,
        const float* __restrict__ W) {
    const int side = blockIdx.x >> 4;        // 0 = K, 1 = Q
    const int a    = blockIdx.x & 15;
    const float* Wx = side ? Wq : Wk;
    const float* bx = side ? bq : bk;

    const int t  = threadIdx.x;
    const int d  = t & 127;
    const int ep = t >> 7;                   // e-partition 0..3

    float w[32];
#pragma unroll
    for (int i = 0; i < 32; i++)
        w[i] = Wx[(ep * 32 + i) * D_ + d];

    __shared__ float Wsh[IDM_ * RR_];        // W[a] : [128,3]
    __shared__ float red[4][IDM_ * RR_];     // partial sums

    for (int i = t; i < IDM_ * RR_; i += 512) Wsh[i] = W[a * IDM_ * RR_ + i];
    __syncthreads();

    float a0 = 0.f, a1 = 0.f, a2 = 0.f;
#pragma unroll
    for (int i = 0; i < 32; i++) {
        int e = ep * 32 + i;
        a0 = fmaf(w[i], Wsh[e * 3 + 0], a0);
        a1 = fmaf(w[i], Wsh[e * 3 + 1], a1);
        a2 = fmaf(w[i], Wsh[e * 3 + 2], a2);
    }
    red[ep][d * 3 + 0] = a0;
    red[ep][d * 3 + 1] = a1;
    red[ep][d * 3 + 2] = a2;
    __syncthreads();

    if (ep == 0) {
        int base = a * (IDM_ * RR_) + d * RR_;
#pragma unroll
        for (int r = 0; r < RR_; r++) {
            int i = d * 3 + r;
            g_M[side][base + r] = red[0][i] + red[1][i] + red[2][i] + red[3][i];
        }
    }

    if (t < 32) {   // bias fold on warp 0
        float c0 = 0.f, c1 = 0.f, c2 = 0.f;
#pragma unroll
        for (int e = t; e < IDM_; e += 32) {
            float b = bx[e];
            c0 = fmaf(b, Wsh[e * 3 + 0], c0);
            c1 = fmaf(b, Wsh[e * 3 + 1], c1);
            c2 = fmaf(b, Wsh[e * 3 + 2], c2);
        }
#pragma unroll
        for (int o = 16; o > 0; o >>= 1) {
            c0 += __shfl_xor_sync(0xffffffffu, c0, o);
            c1 += __shfl_xor_sync(0xffffffffu, c1, o);
            c2 += __shfl_xor_sync(0xffffffffu, c2, o);
        }
        if (t == 0) {
            g_c[side][a * RR_ + 0] = c0;
            g_c[side][a * RR_ + 1] = c1;
            g_c[side][a * RR_ + 2] = c2;
        }
    }
    // Results committed (memory ordered by kernel-completion for the PDL
    // consumer's cudaGridDependencySynchronize).
    cudaTriggerProgrammaticLaunchCompletion();
}

// ---------------------------------------------------------------------------
// Kernel 2 (R14 config, proven best): 8 rows per warp (MLP=8).
// PDL: X loads issued BEFORE cudaGridDependencySynchronize() — they don't
// depend on prep, so they overlap prep's tail.
// ---------------------------------------------------------------------------
__global__ void __launch_bounds__(256, 2) code_kernel(
        const float* __restrict__ K, const float* __restrict__ Q) {
    int warp = (blockIdx.x * blockDim.x + threadIdx.x) >> 5;
    int lane = threadIdx.x & 31;
    int grow0 = warp * 8;                    // 8 consecutive rows, same (side,a)
    int which = (grow0 >= A_ * SK_) ? 1 : 0;
    int row0  = which ? (grow0 - A_ * SK_) : grow0;
    int a     = row0 >> 11;

    const float* X = which ? Q : K;
    const float4* Xv = reinterpret_cast<const float4*>(X);
    float4 x[8];
#pragma unroll
    for (int i = 0; i < 8; i++)
        x[i] = Xv[(row0 + i) * (D_ / 4) + lane];

    // Wait for prep's grid (no-op if prep already finished).
    cudaGridDependencySynchronize();

    const float* M = &g_M[which][a * (IDM_ * RR_) + lane * 12];
    float4 m0 = *reinterpret_cast<const float4*>(M);
    float4 m1 = *reinterpret_cast<const float4*>(M + 4);
    float4 m2 = *reinterpret_cast<const float4*>(M + 8);

    float p0[8], p1[8], p2[8];
#pragma unroll
    for (int i = 0; i < 8; i++) {
        p0[i] = x[i].x * m0.x + x[i].y * m0.w + x[i].z * m1.z + x[i].w * m2.y;
        p1[i] = x[i].x * m0.y + x[i].y * m1.x + x[i].z * m1.w + x[i].w * m2.z;
        p2[i] = x[i].x * m0.z + x[i].y * m1.y + x[i].z * m2.x + x[i].w * m2.w;
    }

#pragma unroll
    for (int o = 16; o > 0; o >>= 1) {       // 24 interleaved chains
#pragma unroll
        for (int i = 0; i < 8; i++) {
            p0[i] += __shfl_xor_sync(0xffffffffu, p0[i], o);
            p1[i] += __shfl_xor_sync(0xffffffffu, p1[i], o);
            p2[i] += __shfl_xor_sync(0xffffffffu, p2[i], o);
        }
    }

    if (lane < 8) {
        float s0, s1, s2;
#pragma unroll
        for (int i = 0; i < 8; i++)
            if (lane == i) { s0 = p0[i]; s1 = p1[i]; s2 = p2[i]; }
        const float* c = &g_c[which][a * RR_];
        float scale = which ? 1.0f : (1.0f / 3.0f);   // fold /R into Kc
        float v0 = tanhf((s0 + c[0]) * 0.1f) * scale;
        float v1 = tanhf((s1 + c[1]) * 0.1f) * scale;
        float v2 = tanhf((s2 + c[2]) * 0.1f) * scale;
        g_code[which][row0 + lane] = make_float4(v0, v1, v2, 0.f);
    }
    cudaTriggerProgrammaticLaunchCompletion();
}

// ---------------------------------------------------------------------------
// Kernel 3 (R14 version): 16 t-rows x 1024 s-cols, streaming stores.
// PDL: prologue/ramp overlaps code's tail; sync before reading g_code.
// ---------------------------------------------------------------------------
__device__ __forceinline__ float pc_fn(const float4 q, const float4 k) {
    float x  = fmaf(q.x, k.x, fmaf(q.y, k.y, q.z * k.z));      // Kc already /3
    float t  = x * x;
    float sg = fmaf(x, fmaf(t, -2.0833333e-5f, 0.025f), 0.5f); // sigmoid(x/10)
    return x * sg;
}

__global__ void __launch_bounds__(256) pc_kernel(float* __restrict__ out) {
    const int a     = blockIdx.z;
    const int tbase = blockIdx.y * 16;
    const int sbase = blockIdx.x * 1024;
    const int tid   = threadIdx.x;

    // Address math before the dependency sync (overlap code's tail).
    const float4* kc  = &g_code[0][a * SK_ + sbase + tid * 4];
    const float4* qcg = &g_code[1][a * SQ_ + tbase];
    float* obase = out + ((size_t)(a * SQ_ + tbase)) * SK_ + (size_t)(sbase + tid * 4);

    cudaGridDependencySynchronize();

    __shared__ float4 qc_sh[16];
    if (tid < 16)
        qc_sh[tid] = qcg[tid];

    const float4 k0 = kc[0];
    const float4 k1 = kc[1];
    const float4 k2 = kc[2];
    const float4 k3 = kc[3];
    __syncthreads();

#pragma unroll 4
    for (int j = 0; j < 16; j++) {
        const float4 q = qc_sh[j];        // broadcast LDS
        float4 o;
        o.x = pc_fn(q, k0);
        o.y = pc_fn(q, k1);
        o.z = pc_fn(q, k2);
        o.w = pc_fn(q, k3);
        __stcs(reinterpret_cast<float4*>(obase + (size_t)j * SK_), o);
    }
}

// ---------------------------------------------------------------------------
// Launch — code and pc use programmatic dependent launch to overlap ramps.
// ---------------------------------------------------------------------------
extern "C" void kernel_launch(void* const* d_in, const int* in_sizes, int n_in,
                              void* d_out, int out_size) {
    const float* K  = (const float*)d_in[0];
    const float* Q  = (const float*)d_in[1];
    const float* Wk = (const float*)d_in[2];
    const float* bk = (const float*)d_in[3];
    const float* Wq = (const float*)d_in[4];
    const float* bq = (const float*)d_in[5];
    const float* W  = (const float*)d_in[6];
    float* out = (float*)d_out;

    prep_kernel<<<2 * A_, 512>>>(Wk, bk, Wq, bq, W);

    cudaLaunchAttribute attr[1];
    attr[0].id = cudaLaunchAttributeProgrammaticStreamSerialization;
    attr[0].val.programmaticStreamSerializationAllowed = 1;

    {
        cudaLaunchConfig_t cfg = {};
        cfg.gridDim  = dim3((2 * A_ * SK_) / 64);
        cfg.blockDim = dim3(256);
        cfg.attrs    = attr;
        cfg.numAttrs = 1;
        cudaLaunchKernelEx(&cfg, code_kernel, K, Q);
    }
    {
        cudaLaunchConfig_t cfg = {};
        cfg.gridDim  = dim3(SK_ / 1024, SQ_ / 16, A_);
        cfg.blockDim = dim3(256);
        cfg.attrs    = attr;
        cfg.numAttrs = 1;
        cudaLaunchKernelEx(&cfg, pc_kernel, out);
    }
}

// round 17
// speedup vs baseline: 1.0347x; 1.0050x over previous
#include <cuda_runtime.h>
#include <math.h>

// Problem constants (fixed by the dataset)
#define A_   16
#define SK_  2048
#define SQ_  2048
#define D_   128
#define IDM_ 128
#define RR_  3
// T_ANNEAL = 10, t_ANNEAL = 0

// ---------------------------------------------------------------------------
// Scratch (device globals — no allocation allowed)
// ---------------------------------------------------------------------------
__device__ float  g_M[2][A_ * IDM_ * RR_];   // folded projections
__device__ float  g_c[2][A_ * RR_];          // folded bias projections
__device__ float4 g_code[2][A_ * SK_];       // [0] = Kc/3, [1] = Qc

// ---------------------------------------------------------------------------
// Kernel 1: fold Wk/Wq + bias via W[a].
// PDL trigger at ENTRY: prep is a single wave (32 blocks), so the trigger
// fires immediately and code launches while prep runs.  Safe because code's
// cudaGridDependencySynchronize waits for prep's full completion+visibility.
// ---------------------------------------------------------------------------
__global__ void __launch_bounds__(512, 1) prep_kernel(
        const float* __restrict__ Wk, const float* __restrict__ bk,
        const float* __restrict__ Wq, const float* __restrict__ bq,
        const float* __restrict__ W) {
    cudaTriggerProgrammaticLaunchCompletion();   // let code launch NOW

    const int side = blockIdx.x >> 4;        // 0 = K, 1 = Q
    const int a    = blockIdx.x & 15;
    const float* Wx = side ? Wq : Wk;
    const float* bx = side ? bq : bk;

    const int t  = threadIdx.x;
    const int d  = t & 127;
    const int ep = t >> 7;                   // e-partition 0..3

    float w[32];
#pragma unroll
    for (int i = 0; i < 32; i++)
        w[i] = Wx[(ep * 32 + i) * D_ + d];

    __shared__ float Wsh[IDM_ * RR_];        // W[a] : [128,3]
    __shared__ float red[4][IDM_ * RR_];     // partial sums

    for (int i = t; i < IDM_ * RR_; i += 512) Wsh[i] = W[a * IDM_ * RR_ + i];
    __syncthreads();

    float a0 = 0.f, a1 = 0.f, a2 = 0.f;
#pragma unroll
    for (int i = 0; i < 32; i++) {
        int e = ep * 32 + i;
        a0 = fmaf(w[i], Wsh[e * 3 + 0], a0);
        a1 = fmaf(w[i], Wsh[e * 3 + 1], a1);
        a2 = fmaf(w[i], Wsh[e * 3 + 2], a2);
    }
    red[ep][d * 3 + 0] = a0;
    red[ep][d * 3 + 1] = a1;
    red[ep][d * 3 + 2] = a2;
    __syncthreads();

    if (ep == 0) {
        int base = a * (IDM_ * RR_) + d * RR_;
#pragma unroll
        for (int r = 0; r < RR_; r++) {
            int i = d * 3 + r;
            g_M[side][base + r] = red[0][i] + red[1][i] + red[2][i] + red[3][i];
        }
    }

    if (t < 32) {   // bias fold on warp 0
        float c0 = 0.f, c1 = 0.f, c2 = 0.f;
#pragma unroll
        for (int e = t; e < IDM_; e += 32) {
            float b = bx[e];
            c0 = fmaf(b, Wsh[e * 3 + 0], c0);
            c1 = fmaf(b, Wsh[e * 3 + 1], c1);
            c2 = fmaf(b, Wsh[e * 3 + 2], c2);
        }
#pragma unroll
        for (int o = 16; o > 0; o >>= 1) {
            c0 += __shfl_xor_sync(0xffffffffu, c0, o);
            c1 += __shfl_xor_sync(0xffffffffu, c1, o);
            c2 += __shfl_xor_sync(0xffffffffu, c2, o);
        }
        if (t == 0) {
            g_c[side][a * RR_ + 0] = c0;
            g_c[side][a * RR_ + 1] = c1;
            g_c[side][a * RR_ + 2] = c2;
        }
    }
}

// ---------------------------------------------------------------------------
// Kernel 2 (R14 config): 8 rows per warp (MLP=8).
// X loads issued before cudaGridDependencySynchronize -> overlap prep's body.
// ---------------------------------------------------------------------------
__global__ void __launch_bounds__(256, 2) code_kernel(
        const float* __restrict__ K, const float* __restrict__ Q) {
    int warp = (blockIdx.x * blockDim.x + threadIdx.x) >> 5;
    int lane = threadIdx.x & 31;
    int grow0 = warp * 8;                    // 8 consecutive rows, same (side,a)
    int which = (grow0 >= A_ * SK_) ? 1 : 0;
    int row0  = which ? (grow0 - A_ * SK_) : grow0;
    int a     = row0 >> 11;

    const float* X = which ? Q : K;
    const float4* Xv = reinterpret_cast<const float4*>(X);
    float4 x[8];
#pragma unroll
    for (int i = 0; i < 8; i++)
        x[i] = Xv[(row0 + i) * (D_ / 4) + lane];

    // Wait for prep's grid (X loads above already in flight).
    cudaGridDependencySynchronize();

    const float* M = &g_M[which][a * (IDM_ * RR_) + lane * 12];
    float4 m0 = *reinterpret_cast<const float4*>(M);
    float4 m1 = *reinterpret_cast<const float4*>(M + 4);
    float4 m2 = *reinterpret_cast<const float4*>(M + 8);

    float p0[8], p1[8], p2[8];
#pragma unroll
    for (int i = 0; i < 8; i++) {
        p0[i] = x[i].x * m0.x + x[i].y * m0.w + x[i].z * m1.z + x[i].w * m2.y;
        p1[i] = x[i].x * m0.y + x[i].y * m1.x + x[i].z * m1.w + x[i].w * m2.z;
        p2[i] = x[i].x * m0.z + x[i].y * m1.y + x[i].z * m2.x + x[i].w * m2.w;
    }

#pragma unroll
    for (int o = 16; o > 0; o >>= 1) {       // 24 interleaved chains
#pragma unroll
        for (int i = 0; i < 8; i++) {
            p0[i] += __shfl_xor_sync(0xffffffffu, p0[i], o);
            p1[i] += __shfl_xor_sync(0xffffffffu, p1[i], o);
            p2[i] += __shfl_xor_sync(0xffffffffu, p2[i], o);
        }
    }

    if (lane < 8) {
        float s0, s1, s2;
#pragma unroll
        for (int i = 0; i < 8; i++)
            if (lane == i) { s0 = p0[i]; s1 = p1[i]; s2 = p2[i]; }
        const float* c = &g_c[which][a * RR_];
        float scale = which ? 1.0f : (1.0f / 3.0f);   // fold /R into Kc
        float v0 = tanhf((s0 + c[0]) * 0.1f) * scale;
        float v1 = tanhf((s1 + c[1]) * 0.1f) * scale;
        float v2 = tanhf((s2 + c[2]) * 0.1f) * scale;
        g_code[which][row0 + lane] = make_float4(v0, v1, v2, 0.f);
    }
    cudaTriggerProgrammaticLaunchCompletion();
}

// ---------------------------------------------------------------------------
// Kernel 3 (R14 version): 16 t-rows x 1024 s-cols, streaming stores.
// ---------------------------------------------------------------------------
__device__ __forceinline__ float pc_fn(const float4 q, const float4 k) {
    float x  = fmaf(q.x, k.x, fmaf(q.y, k.y, q.z * k.z));      // Kc already /3
    float t  = x * x;
    float sg = fmaf(x, fmaf(t, -2.0833333e-5f, 0.025f), 0.5f); // sigmoid(x/10)
    return x * sg;
}

__global__ void __launch_bounds__(256) pc_kernel(float* __restrict__ out) {
    const int a     = blockIdx.z;
    const int tbase = blockIdx.y * 16;
    const int sbase = blockIdx.x * 1024;
    const int tid   = threadIdx.x;

    const float4* kc  = &g_code[0][a * SK_ + sbase + tid * 4];
    const float4* qcg = &g_code[1][a * SQ_ + tbase];
    float* obase = out + ((size_t)(a * SQ_ + tbase)) * SK_ + (size_t)(sbase + tid * 4);

    cudaGridDependencySynchronize();

    __shared__ float4 qc_sh[16];
    if (tid < 16)
        qc_sh[tid] = qcg[tid];

    const float4 k0 = kc[0];
    const float4 k1 = kc[1];
    const float4 k2 = kc[2];
    const float4 k3 = kc[3];
    __syncthreads();

#pragma unroll 4
    for (int j = 0; j < 16; j++) {
        const float4 q = qc_sh[j];        // broadcast LDS
        float4 o;
        o.x = pc_fn(q, k0);
        o.y = pc_fn(q, k1);
        o.z = pc_fn(q, k2);
        o.w = pc_fn(q, k3);
        __stcs(reinterpret_cast<float4*>(obase + (size_t)j * SK_), o);
    }
}

// ---------------------------------------------------------------------------
// Launch — PDL chain: prep -> code -> pc.
// ---------------------------------------------------------------------------
extern "C" void kernel_launch(void* const* d_in, const int* in_sizes, int n_in,
                              void* d_out, int out_size) {
    const float* K  = (const float*)d_in[0];
    const float* Q  = (const float*)d_in[1];
    const float* Wk = (const float*)d_in[2];
    const float* bk = (const float*)d_in[3];
    const float* Wq = (const float*)d_in[4];
    const float* bq = (const float*)d_in[5];
    const float* W  = (const float*)d_in[6];
    float* out = (float*)d_out;

    prep_kernel<<<2 * A_, 512>>>(Wk, bk, Wq, bq, W);

    cudaLaunchAttribute attr[1];
    attr[0].id = cudaLaunchAttributeProgrammaticStreamSerialization;
    attr[0].val.programmaticStreamSerializationAllowed = 1;

    {
        cudaLaunchConfig_t cfg = {};
        cfg.gridDim  = dim3((2 * A_ * SK_) / 64);
        cfg.blockDim = dim3(256);
        cfg.attrs    = attr;
        cfg.numAttrs = 1;
        cudaLaunchKernelEx(&cfg, code_kernel, K, Q);
    }
    {
        cudaLaunchConfig_t cfg = {};
        cfg.gridDim  = dim3(SK_ / 1024, SQ_ / 16, A_);
        cfg.blockDim = dim3(256);
        cfg.attrs    = attr;
        cfg.numAttrs = 1;
        cudaLaunchKernelEx(&cfg, pc_kernel, out);
    }
}